// round 11
// baseline (speedup 1.0000x reference)
#include <cuda_runtime.h>
#include <cuda_bf16.h>

// Segment-wise mean(|diff|): x flattened is [num_segs, L] contiguous.
// out[g] = mean_{i=0..L-2} |x[g*L+i+1] - x[g*L+i]|
//
// Fast path: one warp handles TWO consecutive segments (contiguous 2*L
// floats). Single L2 prefetch prologue covers both segments, so segment B
// is fully L2-resident one segment-duration before its demand loads (ideal
// prefetch distance), and CTA count / prologue overhead is halved.
// Per-segment body is the proven R5 pipeline: double-buffered BATCH=4
// chunks of 32 float4 (2 KB/batch), .cs (evict-first) demand loads,
// rotating-shuffle junctions. No smem, no __syncthreads.

#define BATCH 4

__device__ __forceinline__ float seg_sum_pipe(
    const float4* __restrict__ pseg, int nbatches, int lane)
{
    const float4* __restrict__ p4 = pseg + lane;

    float4 buf[BATCH];
    #pragma unroll
    for (int i = 0; i < BATCH; i++)
        buf[i] = __ldcs(p4 + i * 32);

    float sum = 0.0f;

    for (int b = 1; b < nbatches; b++) {
        float4 nbuf[BATCH];
        const float4* q = p4 + b * (BATCH * 32);
        #pragma unroll
        for (int i = 0; i < BATCH; i++)
            nbuf[i] = __ldcs(q + i * 32);

        #pragma unroll
        for (int i = 0; i < BATCH; i++) {
            const float nextx = (i < BATCH - 1) ? buf[i + 1].x : nbuf[0].x;
            const float src = (lane == 0) ? nextx : buf[i].x;
            const float nx  = __shfl_sync(0xFFFFFFFFu, src, (lane + 1) & 31);
            sum += fabsf(buf[i].y - buf[i].x) + fabsf(buf[i].z - buf[i].y)
                 + fabsf(buf[i].w - buf[i].z) + fabsf(nx - buf[i].w);
        }
        #pragma unroll
        for (int i = 0; i < BATCH; i++) buf[i] = nbuf[i];
    }

    // Final batch: last chunk's lane 31 has no successor (segment end).
    #pragma unroll
    for (int i = 0; i < BATCH; i++) {
        const float nextx = (i < BATCH - 1) ? buf[i + 1].x : buf[i].x;
        const float src = (lane == 0) ? nextx : buf[i].x;
        float nx = __shfl_sync(0xFFFFFFFFu, src, (lane + 1) & 31);
        if (i == BATCH - 1 && lane == 31) nx = buf[i].w;  // zero contribution
        sum += fabsf(buf[i].y - buf[i].x) + fabsf(buf[i].z - buf[i].y)
             + fabsf(buf[i].w - buf[i].z) + fabsf(nx - buf[i].w);
    }
    return sum;
}

__global__ __launch_bounds__(256) void seg_warp_pipe2_kernel(
    const float* __restrict__ x,
    float* __restrict__ out,
    int n4,         // float4s per segment (L/4), multiple of 128
    int nbatches,   // n4 / (32*BATCH), >= 2
    float inv,      // 1/(L-1)
    int num_segs)
{
    const int gwarp = (blockIdx.x * 256 + threadIdx.x) >> 5;
    const int lane  = threadIdx.x & 31;
    const int segA  = gwarp * 2;
    if (segA >= num_segs) return;
    const bool haveB = (segA + 1) < num_segs;

    const float4* __restrict__ pA =
        reinterpret_cast<const float4*>(x) + (long long)segA * n4;

    // L2 prefetch prologue covering BOTH segments. Segment A's first 16
    // lines (batch 0) are demand-loaded immediately, so start at line 16;
    // all of segment B is prefetched (demand arrives a segment later).
    {
        const char* base = reinterpret_cast<const char*>(pA);
        const int nlines = (n4 >> 3) << (haveB ? 1 : 0);  // lines across A(+B)
        for (int ln = 16 + lane; ln < nlines; ln += 32) {
            asm volatile("prefetch.global.L2 [%0];"
                         :: "l"(base + (long long)ln * 128));
        }
    }

    float sumA = seg_sum_pipe(pA, nbatches, lane);

    float sumB = 0.0f;
    if (haveB)
        sumB = seg_sum_pipe(pA + n4, nbatches, lane);

    // Warp reductions; lane 0 writes both means.
    #pragma unroll
    for (int off = 16; off > 0; off >>= 1) {
        sumA += __shfl_down_sync(0xFFFFFFFFu, sumA, off);
        sumB += __shfl_down_sync(0xFFFFFFFFu, sumB, off);
    }
    if (lane == 0) {
        out[segA] = sumA * inv;
        if (haveB) out[segA + 1] = sumB * inv;
    }
}

// Mid path: warp per segment, simple loop (L multiple of 128 floats).
__global__ __launch_bounds__(256) void seg_warp_kernel(
    const float* __restrict__ x,
    float* __restrict__ out,
    int n4, int nchunks, float inv, int num_segs)
{
    const int gwarp = (blockIdx.x * 256 + threadIdx.x) >> 5;
    const int lane  = threadIdx.x & 31;
    if (gwarp >= num_segs) return;

    const float4* __restrict__ p4 =
        reinterpret_cast<const float4*>(x) + (long long)gwarp * n4;

    float sum = 0.0f;
    float4 v = __ldg(p4 + lane);

    #pragma unroll 4
    for (int c = 1; c < nchunks; c++) {
        float4 nv = __ldg(p4 + c * 32 + lane);
        float src = (lane == 0) ? nv.x : v.x;
        float nx  = __shfl_sync(0xFFFFFFFFu, src, (lane + 1) & 31);
        sum += fabsf(v.y - v.x) + fabsf(v.z - v.y)
             + fabsf(v.w - v.z) + fabsf(nx  - v.w);
        v = nv;
    }
    {
        float nx = __shfl_sync(0xFFFFFFFFu, v.x, (lane + 1) & 31);
        if (lane == 31) nx = v.w;
        sum += fabsf(v.y - v.x) + fabsf(v.z - v.y)
             + fabsf(v.w - v.z) + fabsf(nx  - v.w);
    }

    #pragma unroll
    for (int off = 16; off > 0; off >>= 1)
        sum += __shfl_down_sync(0xFFFFFFFFu, sum, off);
    if (lane == 0)
        out[gwarp] = sum * inv;
}

// Generic fallback: one CTA per segment, scalar loads (any L >= 2).
__global__ __launch_bounds__(256) void seg_generic_kernel(
    const float* __restrict__ x,
    float* __restrict__ out,
    int L, float inv)
{
    const long long seg = blockIdx.x;
    const float* __restrict__ p = x + seg * (long long)L;
    const int tid = threadIdx.x;

    float sum = 0.0f;
    for (int i = tid; i < L - 1; i += blockDim.x)
        sum += fabsf(__ldg(p + i + 1) - __ldg(p + i));

    #pragma unroll
    for (int off = 16; off > 0; off >>= 1)
        sum += __shfl_down_sync(0xFFFFFFFFu, sum, off);

    __shared__ float wsum[8];
    const int lane = tid & 31, wid = tid >> 5;
    if (lane == 0) wsum[wid] = sum;
    __syncthreads();
    if (wid == 0) {
        float s = (lane < 8) ? wsum[lane] : 0.0f;
        #pragma unroll
        for (int off = 4; off > 0; off >>= 1)
            s += __shfl_down_sync(0xFFFFFFFFu, s, off);
        if (lane == 0) out[seg] = s * inv;
    }
}

extern "C" void kernel_launch(void* const* d_in, const int* in_sizes, int n_in,
                              void* d_out, int out_size)
{
    const float* x = (const float*)d_in[0];
    float* out = (float*)d_out;

    const long long total = (long long)in_sizes[0];
    const int num_segs = out_size;                     // B * target_len
    const int L = (int)(total / (long long)num_segs);  // segment length
    const float inv = 1.0f / (float)(L - 1);

    if ((L % (BATCH * 128)) == 0 && L / (BATCH * 128) >= 2) {
        const int n4 = L >> 2;
        const int nbatches = n4 / (BATCH * 32);
        const int npairs = (num_segs + 1) / 2;
        const int ctas = (npairs * 32 + 255) / 256;
        seg_warp_pipe2_kernel<<<ctas, 256>>>(x, out, n4, nbatches, inv, num_segs);
    } else if ((L & 127) == 0) {
        const int n4 = L >> 2;
        const int ctas = (num_segs * 32 + 255) / 256;
        seg_warp_kernel<<<ctas, 256>>>(x, out, n4, n4 >> 5, inv, num_segs);
    } else {
        seg_generic_kernel<<<num_segs, 256>>>(x, out, L, inv);
    }
}

// round 12
// speedup vs baseline: 1.0536x; 1.0536x over previous
#include <cuda_runtime.h>
#include <cuda_bf16.h>

// Segment-wise mean(|diff|): x flattened is [num_segs, L] contiguous.
// out[g] = mean_{i=0..L-2} |x[g*L+i+1] - x[g*L+i]|
//
// Fast path (== R10 proven 37.4us, plus one addition): one warp per segment,
// double-buffered pipeline (BATCH=4 chunks of 32 float4 = 2 KB/batch),
// .cs (evict-first) demand loads, L2 prefetch prologue for own lines 16+.
// NEW: each warp also prefetches the FIRST 16 lines (batch 0) of the segment
// one scheduling wave ahead (gwarp + AHEAD), so future warps' batch-0 demand
// loads — the only unprefetched traffic in R10 — hit L2 instead of DRAM.

#define BATCH 4

__global__ __launch_bounds__(256) void seg_warp_pipe_kernel(
    const float* __restrict__ x,
    float* __restrict__ out,
    int n4,         // float4s per segment (L/4), multiple of 128
    int nbatches,   // n4 / (32*BATCH), >= 2
    float inv,      // 1/(L-1)
    int num_segs,
    int ahead)      // warps-in-flight estimate (cross-wave prefetch distance)
{
    const int gwarp = (blockIdx.x * 256 + threadIdx.x) >> 5;
    const int lane  = threadIdx.x & 31;
    if (gwarp >= num_segs) return;

    const float4* __restrict__ pseg =
        reinterpret_cast<const float4*>(x) + (long long)gwarp * n4;
    const float4* __restrict__ p4 = pseg + lane;

    // Own-segment prefetch prologue: lines 16..nlines-1 (batch 0 is demand-
    // loaded immediately below). Register-free in-flight requests.
    {
        const char* base = reinterpret_cast<const char*>(pseg);
        const int nlines = n4 >> 3;
        for (int ln = 16 + lane; ln < nlines; ln += 32) {
            asm volatile("prefetch.global.L2 [%0];" :: "l"(base + (long long)ln * 128));
        }
    }

    // Cross-wave prefetch: batch-0 lines (0..15) of the segment one wave
    // ahead. Issued ~one CTA-lifetime before that warp's demand loads.
    {
        const int aw = gwarp + ahead;
        if (aw < num_segs && lane < 16) {
            const char* abase = reinterpret_cast<const char*>(x)
                              + (long long)aw * n4 * 16;
            asm volatile("prefetch.global.L2 [%0];" :: "l"(abase + lane * 128));
        }
    }

    float4 buf[BATCH];
    #pragma unroll
    for (int i = 0; i < BATCH; i++)
        buf[i] = __ldcs(p4 + i * 32);

    float sum = 0.0f;

    for (int b = 1; b < nbatches; b++) {
        // Issue next batch's loads first (independent of current compute).
        float4 nbuf[BATCH];
        const float4* q = p4 + b * (BATCH * 32);
        #pragma unroll
        for (int i = 0; i < BATCH; i++)
            nbuf[i] = __ldcs(q + i * 32);

        // Compute current batch.
        #pragma unroll
        for (int i = 0; i < BATCH; i++) {
            const float nextx = (i < BATCH - 1) ? buf[i + 1].x : nbuf[0].x;
            const float src = (lane == 0) ? nextx : buf[i].x;
            const float nx  = __shfl_sync(0xFFFFFFFFu, src, (lane + 1) & 31);
            sum += fabsf(buf[i].y - buf[i].x) + fabsf(buf[i].z - buf[i].y)
                 + fabsf(buf[i].w - buf[i].z) + fabsf(nx - buf[i].w);
        }

        #pragma unroll
        for (int i = 0; i < BATCH; i++) buf[i] = nbuf[i];
    }

    // Final batch: last chunk's lane 31 has no successor (segment end).
    #pragma unroll
    for (int i = 0; i < BATCH; i++) {
        const float nextx = (i < BATCH - 1) ? buf[i + 1].x : buf[i].x;
        const float src = (lane == 0) ? nextx : buf[i].x;
        float nx = __shfl_sync(0xFFFFFFFFu, src, (lane + 1) & 31);
        if (i == BATCH - 1 && lane == 31) nx = buf[i].w;  // zero contribution
        sum += fabsf(buf[i].y - buf[i].x) + fabsf(buf[i].z - buf[i].y)
             + fabsf(buf[i].w - buf[i].z) + fabsf(nx - buf[i].w);
    }

    // Warp reduction, lane 0 writes segment mean.
    #pragma unroll
    for (int off = 16; off > 0; off >>= 1)
        sum += __shfl_down_sync(0xFFFFFFFFu, sum, off);
    if (lane == 0)
        out[gwarp] = sum * inv;
}

// Mid path: warp per segment, simple loop (L multiple of 128 floats).
__global__ __launch_bounds__(256) void seg_warp_kernel(
    const float* __restrict__ x,
    float* __restrict__ out,
    int n4, int nchunks, float inv, int num_segs)
{
    const int gwarp = (blockIdx.x * 256 + threadIdx.x) >> 5;
    const int lane  = threadIdx.x & 31;
    if (gwarp >= num_segs) return;

    const float4* __restrict__ p4 =
        reinterpret_cast<const float4*>(x) + (long long)gwarp * n4;

    float sum = 0.0f;
    float4 v = __ldg(p4 + lane);

    #pragma unroll 4
    for (int c = 1; c < nchunks; c++) {
        float4 nv = __ldg(p4 + c * 32 + lane);
        float src = (lane == 0) ? nv.x : v.x;
        float nx  = __shfl_sync(0xFFFFFFFFu, src, (lane + 1) & 31);
        sum += fabsf(v.y - v.x) + fabsf(v.z - v.y)
             + fabsf(v.w - v.z) + fabsf(nx  - v.w);
        v = nv;
    }
    {
        float nx = __shfl_sync(0xFFFFFFFFu, v.x, (lane + 1) & 31);
        if (lane == 31) nx = v.w;
        sum += fabsf(v.y - v.x) + fabsf(v.z - v.y)
             + fabsf(v.w - v.z) + fabsf(nx  - v.w);
    }

    #pragma unroll
    for (int off = 16; off > 0; off >>= 1)
        sum += __shfl_down_sync(0xFFFFFFFFu, sum, off);
    if (lane == 0)
        out[gwarp] = sum * inv;
}

// Generic fallback: one CTA per segment, scalar loads (any L >= 2).
__global__ __launch_bounds__(256) void seg_generic_kernel(
    const float* __restrict__ x,
    float* __restrict__ out,
    int L, float inv)
{
    const long long seg = blockIdx.x;
    const float* __restrict__ p = x + seg * (long long)L;
    const int tid = threadIdx.x;

    float sum = 0.0f;
    for (int i = tid; i < L - 1; i += blockDim.x)
        sum += fabsf(__ldg(p + i + 1) - __ldg(p + i));

    #pragma unroll
    for (int off = 16; off > 0; off >>= 1)
        sum += __shfl_down_sync(0xFFFFFFFFu, sum, off);

    __shared__ float wsum[8];
    const int lane = tid & 31, wid = tid >> 5;
    if (lane == 0) wsum[wid] = sum;
    __syncthreads();
    if (wid == 0) {
        float s = (lane < 8) ? wsum[lane] : 0.0f;
        #pragma unroll
        for (int off = 4; off > 0; off >>= 1)
            s += __shfl_down_sync(0xFFFFFFFFu, s, off);
        if (lane == 0) out[seg] = s * inv;
    }
}

extern "C" void kernel_launch(void* const* d_in, const int* in_sizes, int n_in,
                              void* d_out, int out_size)
{
    const float* x = (const float*)d_in[0];
    float* out = (float*)d_out;

    const long long total = (long long)in_sizes[0];
    const int num_segs = out_size;                     // B * target_len
    const int L = (int)(total / (long long)num_segs);  // segment length
    const float inv = 1.0f / (float)(L - 1);

    const int ctas = (num_segs * 32 + 255) / 256;

    // Cross-wave prefetch distance: ~warps concurrently resident chip-wide.
    // 148 SMs x ~40 resident warps (34-reg kernel at ~65% occupancy).
    const int ahead = 148 * 40;

    if ((L % (BATCH * 128)) == 0 && L / (BATCH * 128) >= 2) {
        const int n4 = L >> 2;
        const int nbatches = n4 / (BATCH * 32);
        seg_warp_pipe_kernel<<<ctas, 256>>>(x, out, n4, nbatches, inv,
                                            num_segs, ahead);
    } else if ((L & 127) == 0) {
        const int n4 = L >> 2;
        seg_warp_kernel<<<ctas, 256>>>(x, out, n4, n4 >> 5, inv, num_segs);
    } else {
        seg_generic_kernel<<<num_segs, 256>>>(x, out, L, inv);
    }
}

// round 13
// speedup vs baseline: 1.1104x; 1.0539x over previous
#include <cuda_runtime.h>
#include <cuda_bf16.h>

// Segment-wise mean(|diff|): x flattened is [num_segs, L] contiguous.
// out[g] = mean_{i=0..L-2} |x[g*L+i+1] - x[g*L+i]|
//
// FINAL (== R10, reproduced twice at 37.4-37.6us; every probed variation
// regressed). One warp per segment; double-buffered load pipeline (BATCH=4
// chunks of 32 float4 = 2 KB per batch, next batch issued before current
// batch's compute); L2 prefetch prologue (register-free MLP) covering lines
// 16+ of the warp's own segment; demand loads use .cs (evict-first) so the
// stream doesn't displace prefetched lines. Cross-vector junctions via one
// rotating shuffle per chunk. No smem, no __syncthreads in the fast path.

#define BATCH 4

__global__ __launch_bounds__(256) void seg_warp_pipe_kernel(
    const float* __restrict__ x,
    float* __restrict__ out,
    int n4,         // float4s per segment (L/4), multiple of 128
    int nbatches,   // n4 / (32*BATCH), >= 2
    float inv,      // 1/(L-1)
    int num_segs)
{
    const int gwarp = (blockIdx.x * 256 + threadIdx.x) >> 5;
    const int lane  = threadIdx.x & 31;
    if (gwarp >= num_segs) return;

    const float4* __restrict__ pseg =
        reinterpret_cast<const float4*>(x) + (long long)gwarp * n4;
    const float4* __restrict__ p4 = pseg + lane;

    // L2 prefetch prologue: pull lines for batches 1..nbatches-1 into L2.
    // Segment has n4/8 128-byte lines; batch 0 (first 16 lines) is demand-
    // loaded immediately below, so start at line 16. Register-free MLP.
    {
        const char* base = reinterpret_cast<const char*>(pseg);
        const int nlines = n4 >> 3;
        for (int ln = 16 + lane; ln < nlines; ln += 32) {
            asm volatile("prefetch.global.L2 [%0];" :: "l"(base + (long long)ln * 128));
        }
    }

    float4 buf[BATCH];
    #pragma unroll
    for (int i = 0; i < BATCH; i++)
        buf[i] = __ldcs(p4 + i * 32);

    float sum = 0.0f;

    for (int b = 1; b < nbatches; b++) {
        // Issue next batch's loads first (independent of current compute).
        float4 nbuf[BATCH];
        const float4* q = p4 + b * (BATCH * 32);
        #pragma unroll
        for (int i = 0; i < BATCH; i++)
            nbuf[i] = __ldcs(q + i * 32);

        // Compute current batch.
        #pragma unroll
        for (int i = 0; i < BATCH; i++) {
            const float nextx = (i < BATCH - 1) ? buf[i + 1].x : nbuf[0].x;
            const float src = (lane == 0) ? nextx : buf[i].x;
            const float nx  = __shfl_sync(0xFFFFFFFFu, src, (lane + 1) & 31);
            sum += fabsf(buf[i].y - buf[i].x) + fabsf(buf[i].z - buf[i].y)
                 + fabsf(buf[i].w - buf[i].z) + fabsf(nx - buf[i].w);
        }

        #pragma unroll
        for (int i = 0; i < BATCH; i++) buf[i] = nbuf[i];
    }

    // Final batch: last chunk's lane 31 has no successor (segment end).
    #pragma unroll
    for (int i = 0; i < BATCH; i++) {
        const float nextx = (i < BATCH - 1) ? buf[i + 1].x : buf[i].x;
        const float src = (lane == 0) ? nextx : buf[i].x;
        float nx = __shfl_sync(0xFFFFFFFFu, src, (lane + 1) & 31);
        if (i == BATCH - 1 && lane == 31) nx = buf[i].w;  // zero contribution
        sum += fabsf(buf[i].y - buf[i].x) + fabsf(buf[i].z - buf[i].y)
             + fabsf(buf[i].w - buf[i].z) + fabsf(nx - buf[i].w);
    }

    // Warp reduction, lane 0 writes segment mean.
    #pragma unroll
    for (int off = 16; off > 0; off >>= 1)
        sum += __shfl_down_sync(0xFFFFFFFFu, sum, off);
    if (lane == 0)
        out[gwarp] = sum * inv;
}

// Mid path: warp per segment, simple loop (L multiple of 128 floats).
__global__ __launch_bounds__(256) void seg_warp_kernel(
    const float* __restrict__ x,
    float* __restrict__ out,
    int n4, int nchunks, float inv, int num_segs)
{
    const int gwarp = (blockIdx.x * 256 + threadIdx.x) >> 5;
    const int lane  = threadIdx.x & 31;
    if (gwarp >= num_segs) return;

    const float4* __restrict__ p4 =
        reinterpret_cast<const float4*>(x) + (long long)gwarp * n4;

    float sum = 0.0f;
    float4 v = __ldg(p4 + lane);

    #pragma unroll 4
    for (int c = 1; c < nchunks; c++) {
        float4 nv = __ldg(p4 + c * 32 + lane);
        float src = (lane == 0) ? nv.x : v.x;
        float nx  = __shfl_sync(0xFFFFFFFFu, src, (lane + 1) & 31);
        sum += fabsf(v.y - v.x) + fabsf(v.z - v.y)
             + fabsf(v.w - v.z) + fabsf(nx  - v.w);
        v = nv;
    }
    {
        float nx = __shfl_sync(0xFFFFFFFFu, v.x, (lane + 1) & 31);
        if (lane == 31) nx = v.w;
        sum += fabsf(v.y - v.x) + fabsf(v.z - v.y)
             + fabsf(v.w - v.z) + fabsf(nx  - v.w);
    }

    #pragma unroll
    for (int off = 16; off > 0; off >>= 1)
        sum += __shfl_down_sync(0xFFFFFFFFu, sum, off);
    if (lane == 0)
        out[gwarp] = sum * inv;
}

// Generic fallback: one CTA per segment, scalar loads (any L >= 2).
__global__ __launch_bounds__(256) void seg_generic_kernel(
    const float* __restrict__ x,
    float* __restrict__ out,
    int L, float inv)
{
    const long long seg = blockIdx.x;
    const float* __restrict__ p = x + seg * (long long)L;
    const int tid = threadIdx.x;

    float sum = 0.0f;
    for (int i = tid; i < L - 1; i += blockDim.x)
        sum += fabsf(__ldg(p + i + 1) - __ldg(p + i));

    #pragma unroll
    for (int off = 16; off > 0; off >>= 1)
        sum += __shfl_down_sync(0xFFFFFFFFu, sum, off);

    __shared__ float wsum[8];
    const int lane = tid & 31, wid = tid >> 5;
    if (lane == 0) wsum[wid] = sum;
    __syncthreads();
    if (wid == 0) {
        float s = (lane < 8) ? wsum[lane] : 0.0f;
        #pragma unroll
        for (int off = 4; off > 0; off >>= 1)
            s += __shfl_down_sync(0xFFFFFFFFu, s, off);
        if (lane == 0) out[seg] = s * inv;
    }
}

extern "C" void kernel_launch(void* const* d_in, const int* in_sizes, int n_in,
                              void* d_out, int out_size)
{
    const float* x = (const float*)d_in[0];
    float* out = (float*)d_out;

    const long long total = (long long)in_sizes[0];
    const int num_segs = out_size;                     // B * target_len
    const int L = (int)(total / (long long)num_segs);  // segment length
    const float inv = 1.0f / (float)(L - 1);

    const int ctas = (num_segs * 32 + 255) / 256;

    if ((L % (BATCH * 128)) == 0 && L / (BATCH * 128) >= 2) {
        const int n4 = L >> 2;
        const int nbatches = n4 / (BATCH * 32);
        seg_warp_pipe_kernel<<<ctas, 256>>>(x, out, n4, nbatches, inv, num_segs);
    } else if ((L & 127) == 0) {
        const int n4 = L >> 2;
        seg_warp_kernel<<<ctas, 256>>>(x, out, n4, n4 >> 5, inv, num_segs);
    } else {
        seg_generic_kernel<<<num_segs, 256>>>(x, out, L, inv);
    }
}

// round 14
// speedup vs baseline: 1.1664x; 1.0504x over previous
#include <cuda_runtime.h>
#include <cuda_bf16.h>

// Segment-wise mean(|diff|): x flattened is [num_segs, L] contiguous.
// out[g] = mean_{i=0..L-2} |x[g*L+i+1] - x[g*L+i]|
//
// FINAL+micro: identical to the thrice-reproduced 37.4us kernel (one warp
// per segment, double-buffered BATCH=4 pipeline, .cs demand loads, L2
// prefetch prologue for lines 16+), with ONE reorder: batch-0 demand loads
// (critical path, not covered by prefetch) issue BEFORE the 48-instruction
// prefetch prologue, removing ~50-100 cycles of warp-startup serialization.

#define BATCH 4

__global__ __launch_bounds__(256) void seg_warp_pipe_kernel(
    const float* __restrict__ x,
    float* __restrict__ out,
    int n4,         // float4s per segment (L/4), multiple of 128
    int nbatches,   // n4 / (32*BATCH), >= 2
    float inv,      // 1/(L-1)
    int num_segs)
{
    const int gwarp = (blockIdx.x * 256 + threadIdx.x) >> 5;
    const int lane  = threadIdx.x & 31;
    if (gwarp >= num_segs) return;

    const float4* __restrict__ pseg =
        reinterpret_cast<const float4*>(x) + (long long)gwarp * n4;
    const float4* __restrict__ p4 = pseg + lane;

    // Batch-0 demand loads FIRST (critical path; prefetch doesn't cover them).
    float4 buf[BATCH];
    #pragma unroll
    for (int i = 0; i < BATCH; i++)
        buf[i] = __ldcs(p4 + i * 32);

    // L2 prefetch prologue: lines 16..nlines-1 (batches 1..N-1), issued while
    // batch-0 loads are in flight. Register-free MLP; prefetched lines keep
    // default L2 priority while .cs demand loads stream evict-first.
    {
        const char* base = reinterpret_cast<const char*>(pseg);
        const int nlines = n4 >> 3;
        for (int ln = 16 + lane; ln < nlines; ln += 32) {
            asm volatile("prefetch.global.L2 [%0];" :: "l"(base + (long long)ln * 128));
        }
    }

    float sum = 0.0f;

    for (int b = 1; b < nbatches; b++) {
        // Issue next batch's loads first (independent of current compute).
        float4 nbuf[BATCH];
        const float4* q = p4 + b * (BATCH * 32);
        #pragma unroll
        for (int i = 0; i < BATCH; i++)
            nbuf[i] = __ldcs(q + i * 32);

        // Compute current batch.
        #pragma unroll
        for (int i = 0; i < BATCH; i++) {
            const float nextx = (i < BATCH - 1) ? buf[i + 1].x : nbuf[0].x;
            const float src = (lane == 0) ? nextx : buf[i].x;
            const float nx  = __shfl_sync(0xFFFFFFFFu, src, (lane + 1) & 31);
            sum += fabsf(buf[i].y - buf[i].x) + fabsf(buf[i].z - buf[i].y)
                 + fabsf(buf[i].w - buf[i].z) + fabsf(nx - buf[i].w);
        }

        #pragma unroll
        for (int i = 0; i < BATCH; i++) buf[i] = nbuf[i];
    }

    // Final batch: last chunk's lane 31 has no successor (segment end).
    #pragma unroll
    for (int i = 0; i < BATCH; i++) {
        const float nextx = (i < BATCH - 1) ? buf[i + 1].x : buf[i].x;
        const float src = (lane == 0) ? nextx : buf[i].x;
        float nx = __shfl_sync(0xFFFFFFFFu, src, (lane + 1) & 31);
        if (i == BATCH - 1 && lane == 31) nx = buf[i].w;  // zero contribution
        sum += fabsf(buf[i].y - buf[i].x) + fabsf(buf[i].z - buf[i].y)
             + fabsf(buf[i].w - buf[i].z) + fabsf(nx - buf[i].w);
    }

    // Warp reduction, lane 0 writes segment mean.
    #pragma unroll
    for (int off = 16; off > 0; off >>= 1)
        sum += __shfl_down_sync(0xFFFFFFFFu, sum, off);
    if (lane == 0)
        out[gwarp] = sum * inv;
}

// Mid path: warp per segment, simple loop (L multiple of 128 floats).
__global__ __launch_bounds__(256) void seg_warp_kernel(
    const float* __restrict__ x,
    float* __restrict__ out,
    int n4, int nchunks, float inv, int num_segs)
{
    const int gwarp = (blockIdx.x * 256 + threadIdx.x) >> 5;
    const int lane  = threadIdx.x & 31;
    if (gwarp >= num_segs) return;

    const float4* __restrict__ p4 =
        reinterpret_cast<const float4*>(x) + (long long)gwarp * n4;

    float sum = 0.0f;
    float4 v = __ldg(p4 + lane);

    #pragma unroll 4
    for (int c = 1; c < nchunks; c++) {
        float4 nv = __ldg(p4 + c * 32 + lane);
        float src = (lane == 0) ? nv.x : v.x;
        float nx  = __shfl_sync(0xFFFFFFFFu, src, (lane + 1) & 31);
        sum += fabsf(v.y - v.x) + fabsf(v.z - v.y)
             + fabsf(v.w - v.z) + fabsf(nx  - v.w);
        v = nv;
    }
    {
        float nx = __shfl_sync(0xFFFFFFFFu, v.x, (lane + 1) & 31);
        if (lane == 31) nx = v.w;
        sum += fabsf(v.y - v.x) + fabsf(v.z - v.y)
             + fabsf(v.w - v.z) + fabsf(nx  - v.w);
    }

    #pragma unroll
    for (int off = 16; off > 0; off >>= 1)
        sum += __shfl_down_sync(0xFFFFFFFFu, sum, off);
    if (lane == 0)
        out[gwarp] = sum * inv;
}

// Generic fallback: one CTA per segment, scalar loads (any L >= 2).
__global__ __launch_bounds__(256) void seg_generic_kernel(
    const float* __restrict__ x,
    float* __restrict__ out,
    int L, float inv)
{
    const long long seg = blockIdx.x;
    const float* __restrict__ p = x + seg * (long long)L;
    const int tid = threadIdx.x;

    float sum = 0.0f;
    for (int i = tid; i < L - 1; i += blockDim.x)
        sum += fabsf(__ldg(p + i + 1) - __ldg(p + i));

    #pragma unroll
    for (int off = 16; off > 0; off >>= 1)
        sum += __shfl_down_sync(0xFFFFFFFFu, sum, off);

    __shared__ float wsum[8];
    const int lane = tid & 31, wid = tid >> 5;
    if (lane == 0) wsum[wid] = sum;
    __syncthreads();
    if (wid == 0) {
        float s = (lane < 8) ? wsum[lane] : 0.0f;
        #pragma unroll
        for (int off = 4; off > 0; off >>= 1)
            s += __shfl_down_sync(0xFFFFFFFFu, s, off);
        if (lane == 0) out[seg] = s * inv;
    }
}

extern "C" void kernel_launch(void* const* d_in, const int* in_sizes, int n_in,
                              void* d_out, int out_size)
{
    const float* x = (const float*)d_in[0];
    float* out = (float*)d_out;

    const long long total = (long long)in_sizes[0];
    const int num_segs = out_size;                     // B * target_len
    const int L = (int)(total / (long long)num_segs);  // segment length
    const float inv = 1.0f / (float)(L - 1);

    const int ctas = (num_segs * 32 + 255) / 256;

    if ((L % (BATCH * 128)) == 0 && L / (BATCH * 128) >= 2) {
        const int n4 = L >> 2;
        const int nbatches = n4 / (BATCH * 32);
        seg_warp_pipe_kernel<<<ctas, 256>>>(x, out, n4, nbatches, inv, num_segs);
    } else if ((L & 127) == 0) {
        const int n4 = L >> 2;
        seg_warp_kernel<<<ctas, 256>>>(x, out, n4, n4 >> 5, inv, num_segs);
    } else {
        seg_generic_kernel<<<num_segs, 256>>>(x, out, L, inv);
    }
}

// round 15
// speedup vs baseline: 1.1759x; 1.0082x over previous
#include <cuda_runtime.h>
#include <cuda_bf16.h>

// Segment-wise mean(|diff|): x flattened is [num_segs, L] contiguous.
// out[g] = mean_{i=0..L-2} |x[g*L+i+1] - x[g*L+i]|
//
// One warp per segment, double-buffered BATCH=4 pipeline, .cs demand loads,
// L2 prefetch prologue. Critical-path ordering (R14 win, extended): batch-0
// AND batch-1 demand loads issue BEFORE the prefetch prologue (8 LDG.128 in
// flight at warp start), prologue covers lines 32+ only. First pipeline
// iteration is peeled accordingly; steady-state loop unchanged.

#define BATCH 4

__global__ __launch_bounds__(256) void seg_warp_pipe_kernel(
    const float* __restrict__ x,
    float* __restrict__ out,
    int n4,         // float4s per segment (L/4), multiple of 128
    int nbatches,   // n4 / (32*BATCH), >= 2
    float inv,      // 1/(L-1)
    int num_segs)
{
    const int gwarp = (blockIdx.x * 256 + threadIdx.x) >> 5;
    const int lane  = threadIdx.x & 31;
    if (gwarp >= num_segs) return;

    const float4* __restrict__ pseg =
        reinterpret_cast<const float4*>(x) + (long long)gwarp * n4;
    const float4* __restrict__ p4 = pseg + lane;

    // Batch-0 and batch-1 demand loads FIRST: 8 independent LDG.128 in
    // flight before any prefetch instructions consume issue slots.
    float4 buf[BATCH];
    #pragma unroll
    for (int i = 0; i < BATCH; i++)
        buf[i] = __ldcs(p4 + i * 32);

    float4 nbuf[BATCH];
    #pragma unroll
    for (int i = 0; i < BATCH; i++)
        nbuf[i] = __ldcs(p4 + (BATCH * 32) + i * 32);

    // L2 prefetch prologue: lines 32..nlines-1 (batches 2..N-1), issued
    // while the 8 demand loads are in flight. Register-free MLP; prefetched
    // lines keep default L2 priority while .cs demand loads stream
    // evict-first.
    {
        const char* base = reinterpret_cast<const char*>(pseg);
        const int nlines = n4 >> 3;
        for (int ln = 32 + lane; ln < nlines; ln += 32) {
            asm volatile("prefetch.global.L2 [%0];" :: "l"(base + (long long)ln * 128));
        }
    }

    float sum = 0.0f;

    // Peeled iteration b=1: compute batch 0 (nbuf = batch 1 already loaded).
    #pragma unroll
    for (int i = 0; i < BATCH; i++) {
        const float nextx = (i < BATCH - 1) ? buf[i + 1].x : nbuf[0].x;
        const float src = (lane == 0) ? nextx : buf[i].x;
        const float nx  = __shfl_sync(0xFFFFFFFFu, src, (lane + 1) & 31);
        sum += fabsf(buf[i].y - buf[i].x) + fabsf(buf[i].z - buf[i].y)
             + fabsf(buf[i].w - buf[i].z) + fabsf(nx - buf[i].w);
    }
    #pragma unroll
    for (int i = 0; i < BATCH; i++) buf[i] = nbuf[i];

    // Steady state: load batch b, compute batch b-1.
    for (int b = 2; b < nbatches; b++) {
        float4 nb[BATCH];
        const float4* q = p4 + b * (BATCH * 32);
        #pragma unroll
        for (int i = 0; i < BATCH; i++)
            nb[i] = __ldcs(q + i * 32);

        #pragma unroll
        for (int i = 0; i < BATCH; i++) {
            const float nextx = (i < BATCH - 1) ? buf[i + 1].x : nb[0].x;
            const float src = (lane == 0) ? nextx : buf[i].x;
            const float nx  = __shfl_sync(0xFFFFFFFFu, src, (lane + 1) & 31);
            sum += fabsf(buf[i].y - buf[i].x) + fabsf(buf[i].z - buf[i].y)
                 + fabsf(buf[i].w - buf[i].z) + fabsf(nx - buf[i].w);
        }
        #pragma unroll
        for (int i = 0; i < BATCH; i++) buf[i] = nb[i];
    }

    // Final batch: last chunk's lane 31 has no successor (segment end).
    #pragma unroll
    for (int i = 0; i < BATCH; i++) {
        const float nextx = (i < BATCH - 1) ? buf[i + 1].x : buf[i].x;
        const float src = (lane == 0) ? nextx : buf[i].x;
        float nx = __shfl_sync(0xFFFFFFFFu, src, (lane + 1) & 31);
        if (i == BATCH - 1 && lane == 31) nx = buf[i].w;  // zero contribution
        sum += fabsf(buf[i].y - buf[i].x) + fabsf(buf[i].z - buf[i].y)
             + fabsf(buf[i].w - buf[i].z) + fabsf(nx - buf[i].w);
    }

    // Warp reduction, lane 0 writes segment mean.
    #pragma unroll
    for (int off = 16; off > 0; off >>= 1)
        sum += __shfl_down_sync(0xFFFFFFFFu, sum, off);
    if (lane == 0)
        out[gwarp] = sum * inv;
}

// Mid path: warp per segment, simple loop (L multiple of 128 floats).
__global__ __launch_bounds__(256) void seg_warp_kernel(
    const float* __restrict__ x,
    float* __restrict__ out,
    int n4, int nchunks, float inv, int num_segs)
{
    const int gwarp = (blockIdx.x * 256 + threadIdx.x) >> 5;
    const int lane  = threadIdx.x & 31;
    if (gwarp >= num_segs) return;

    const float4* __restrict__ p4 =
        reinterpret_cast<const float4*>(x) + (long long)gwarp * n4;

    float sum = 0.0f;
    float4 v = __ldg(p4 + lane);

    #pragma unroll 4
    for (int c = 1; c < nchunks; c++) {
        float4 nv = __ldg(p4 + c * 32 + lane);
        float src = (lane == 0) ? nv.x : v.x;
        float nx  = __shfl_sync(0xFFFFFFFFu, src, (lane + 1) & 31);
        sum += fabsf(v.y - v.x) + fabsf(v.z - v.y)
             + fabsf(v.w - v.z) + fabsf(nx  - v.w);
        v = nv;
    }
    {
        float nx = __shfl_sync(0xFFFFFFFFu, v.x, (lane + 1) & 31);
        if (lane == 31) nx = v.w;
        sum += fabsf(v.y - v.x) + fabsf(v.z - v.y)
             + fabsf(v.w - v.z) + fabsf(nx  - v.w);
    }

    #pragma unroll
    for (int off = 16; off > 0; off >>= 1)
        sum += __shfl_down_sync(0xFFFFFFFFu, sum, off);
    if (lane == 0)
        out[gwarp] = sum * inv;
}

// Generic fallback: one CTA per segment, scalar loads (any L >= 2).
__global__ __launch_bounds__(256) void seg_generic_kernel(
    const float* __restrict__ x,
    float* __restrict__ out,
    int L, float inv)
{
    const long long seg = blockIdx.x;
    const float* __restrict__ p = x + seg * (long long)L;
    const int tid = threadIdx.x;

    float sum = 0.0f;
    for (int i = tid; i < L - 1; i += blockDim.x)
        sum += fabsf(__ldg(p + i + 1) - __ldg(p + i));

    #pragma unroll
    for (int off = 16; off > 0; off >>= 1)
        sum += __shfl_down_sync(0xFFFFFFFFu, sum, off);

    __shared__ float wsum[8];
    const int lane = tid & 31, wid = tid >> 5;
    if (lane == 0) wsum[wid] = sum;
    __syncthreads();
    if (wid == 0) {
        float s = (lane < 8) ? wsum[lane] : 0.0f;
        #pragma unroll
        for (int off = 4; off > 0; off >>= 1)
            s += __shfl_down_sync(0xFFFFFFFFu, s, off);
        if (lane == 0) out[seg] = s * inv;
    }
}

extern "C" void kernel_launch(void* const* d_in, const int* in_sizes, int n_in,
                              void* d_out, int out_size)
{
    const float* x = (const float*)d_in[0];
    float* out = (float*)d_out;

    const long long total = (long long)in_sizes[0];
    const int num_segs = out_size;                     // B * target_len
    const int L = (int)(total / (long long)num_segs);  // segment length
    const float inv = 1.0f / (float)(L - 1);

    const int ctas = (num_segs * 32 + 255) / 256;

    if ((L % (BATCH * 128)) == 0 && L / (BATCH * 128) >= 3) {
        const int n4 = L >> 2;
        const int nbatches = n4 / (BATCH * 32);
        seg_warp_pipe_kernel<<<ctas, 256>>>(x, out, n4, nbatches, inv, num_segs);
    } else if ((L & 127) == 0) {
        const int n4 = L >> 2;
        seg_warp_kernel<<<ctas, 256>>>(x, out, n4, n4 >> 5, inv, num_segs);
    } else {
        seg_generic_kernel<<<num_segs, 256>>>(x, out, L, inv);
    }
}